// round 2
// baseline (speedup 1.0000x reference)
#include <cuda_runtime.h>
#include <math.h>

#define B_ 2
#define T_ 2048
#define C_ 1024
#define H_ 16
#define D_ 64
#define M_ (B_*T_)
#define SCALE 0.125f   // 1/sqrt(64)

// Scratch (allocation-free contract: __device__ globals)
__device__ float g_q[B_*H_*T_*D_];
__device__ float g_k[B_*H_*T_*D_];
__device__ float g_v[B_*H_*T_*D_];
__device__ float g_att[B_*T_*C_];

// ---------------------------------------------------------------------------
// GEMM: out = A[M,K=1024] @ W[N,K=1024]^T + bias[N]
// mode 0: scatter to [B,H,T,D] (QKV proj). mode 1: plain [M,N] (output proj).
// ---------------------------------------------------------------------------
__global__ __launch_bounds__(256)
void gemm64(const float* __restrict__ A, const float* __restrict__ W,
            const float* __restrict__ bias, float* __restrict__ out, int mode)
{
    __shared__ float As[64][17];
    __shared__ float Ws[64][17];
    const int tid = threadIdx.x;
    const int tx = tid & 15, ty = tid >> 4;
    const int m0 = blockIdx.y << 6, n0 = blockIdx.x << 6;

    float acc[4][4];
#pragma unroll
    for (int r = 0; r < 4; r++)
#pragma unroll
        for (int c = 0; c < 4; c++) acc[r][c] = 0.f;

    for (int k0 = 0; k0 < C_; k0 += 16) {
        __syncthreads();
#pragma unroll
        for (int e = tid; e < 64*16; e += 256) {
            int r = e >> 4, c = e & 15;
            As[r][c] = A[(size_t)(m0 + r) * C_ + k0 + c];
            Ws[r][c] = W[(size_t)(n0 + r) * C_ + k0 + c];
        }
        __syncthreads();
#pragma unroll
        for (int kk = 0; kk < 16; kk++) {
            float a[4], w[4];
#pragma unroll
            for (int r = 0; r < 4; r++) a[r] = As[4*ty + r][kk];
#pragma unroll
            for (int c = 0; c < 4; c++) w[c] = Ws[4*tx + c][kk];
#pragma unroll
            for (int r = 0; r < 4; r++)
#pragma unroll
                for (int c = 0; c < 4; c++)
                    acc[r][c] += a[r] * w[c];
        }
    }

#pragma unroll
    for (int r = 0; r < 4; r++) {
        const int m = m0 + 4*ty + r;
#pragma unroll
        for (int c = 0; c < 4; c++) {
            const int n = n0 + 4*tx + c;
            const float val = acc[r][c] + bias[n];
            if (mode == 0) {
                const int b = m >> 11, t = m & (T_-1);
                const int h = n >> 6,  d = n & (D_-1);
                out[(((size_t)(b*H_ + h) * T_) + t) * D_ + d] = val;
            } else {
                out[(size_t)m * C_ + n] = val;
            }
        }
    }
}

// ---------------------------------------------------------------------------
// RoPE on q and k in [B,H,T,D] layout (in-place). Pair i in [0,32).
// ---------------------------------------------------------------------------
__global__ __launch_bounds__(256)
void rope_kernel(float* __restrict__ q, float* __restrict__ k)
{
    const int idx = blockIdx.x * blockDim.x + threadIdx.x;
    const int total = B_*H_*T_*(D_/2);
    if (idx >= total) return;
    const int i  = idx & 31;
    const int t  = (idx >> 5) & (T_-1);
    const int bh = idx >> 16;  // 32*2048 = 65536

    const double inv = pow(10000.0, -(double)i / 32.0);
    const double ang = (double)t * inv;
    const float c = (float)cos(ang);
    const float s = (float)sin(ang);

    const size_t base = ((size_t)bh * T_ + t) * D_ + 2*i;
    float x1 = q[base], x2 = q[base+1];
    q[base]   = x1*c - x2*s;
    q[base+1] = x1*s + x2*c;
    x1 = k[base]; x2 = k[base+1];
    k[base]   = x1*c - x2*s;
    k[base+1] = x1*s + x2*c;
}

// ---------------------------------------------------------------------------
// Flash attention, causal. One block = 64 queries of one (b,h).
// 256 threads, 4x4 register tile per thread. K transposed in smem for
// conflict-free float4 reads; V row-major (also conflict-free float4).
// Writes output directly in [B,T,C] layout.
// ---------------------------------------------------------------------------
#define KT_STRIDE 68  // 68*4B = 272B: keeps 16B alignment, avoids bank conflicts

__global__ __launch_bounds__(256)
void attn_kernel(const float* __restrict__ q, const float* __restrict__ k,
                 const float* __restrict__ v, float* __restrict__ out)
{
    extern __shared__ float smem[];
    float (*Qs)[65]        = (float(*)[65])        smem;                       // 64*65
    float (*Kt)[KT_STRIDE] = (float(*)[KT_STRIDE])(smem + 64*65);              // 64*68 (Kt[d][j])
    float (*Vs)[64]        = (float(*)[64])       (smem + 64*65 + 64*KT_STRIDE);
    float (*Ps)[65]        = (float(*)[65])       (smem + 64*65 + 64*KT_STRIDE + 64*64);

    const int tid = threadIdx.x;
    const int tx = tid & 15, ty = tid >> 4;
    const int bh = blockIdx.y;
    const int b = bh >> 4, h = bh & (H_-1);
    const int q0 = blockIdx.x << 6;

    const float* qb = q + (size_t)bh * T_ * D_;
    const float* kb = k + (size_t)bh * T_ * D_;
    const float* vb = v + (size_t)bh * T_ * D_;

    // load Q tile (coalesced)
    for (int e = tid; e < 64*D_; e += 256) {
        const int r = e >> 6, d = e & 63;
        Qs[r][d] = qb[(size_t)(q0 + r) * D_ + d];
    }

    float m_r[4], l_r[4], acc[4][4];
#pragma unroll
    for (int r = 0; r < 4; r++) {
        m_r[r] = -1e30f; l_r[r] = 0.f;
#pragma unroll
        for (int c = 0; c < 4; c++) acc[r][c] = 0.f;
    }

    const int ntiles = (q0 >> 6) + 1;
    for (int kt = 0; kt < ntiles; kt++) {
        const int k0 = kt << 6;
        __syncthreads();  // prior PV done with Kt/Vs; Qs visible on first iter
        for (int e = tid; e < 64*D_; e += 256) {
            const int j = e >> 6, d = e & 63;
            const float kvr = kb[(size_t)(k0 + j) * D_ + d];
            Kt[d][j] = kvr;
            Vs[j][d] = vb[(size_t)(k0 + j) * D_ + d];
        }
        __syncthreads();

        // scores: s[r][c] = Q[4ty+r] . K[4tx+c]
        float s[4][4];
#pragma unroll
        for (int r = 0; r < 4; r++)
#pragma unroll
            for (int c = 0; c < 4; c++) s[r][c] = 0.f;

#pragma unroll 8
        for (int d = 0; d < D_; d++) {
            const float4 kv = *(const float4*)&Kt[d][4*tx];
            const float kc[4] = {kv.x, kv.y, kv.z, kv.w};
            float qd[4];
#pragma unroll
            for (int r = 0; r < 4; r++) qd[r] = Qs[4*ty + r][d];
#pragma unroll
            for (int r = 0; r < 4; r++)
#pragma unroll
                for (int c = 0; c < 4; c++)
                    s[r][c] += qd[r] * kc[c];
        }

        // mask + online softmax (row groups of 16 lanes -> shfl reduce)
#pragma unroll
        for (int r = 0; r < 4; r++) {
            const int qi = q0 + 4*ty + r;
            float rm = -1e30f;
#pragma unroll
            for (int c = 0; c < 4; c++) {
                const int kj = k0 + 4*tx + c;
                s[r][c] = (kj <= qi) ? s[r][c] * SCALE : -1e30f;
                rm = fmaxf(rm, s[r][c]);
            }
#pragma unroll
            for (int off = 8; off > 0; off >>= 1)
                rm = fmaxf(rm, __shfl_xor_sync(0xffffffffu, rm, off));
            const float mnew = fmaxf(m_r[r], rm);
            const float alpha = __expf(m_r[r] - mnew);
            m_r[r] = mnew;
            float rs = 0.f;
#pragma unroll
            for (int c = 0; c < 4; c++) {
                const float p = __expf(s[r][c] - mnew);
                s[r][c] = p;
                rs += p;
            }
#pragma unroll
            for (int off = 8; off > 0; off >>= 1)
                rs += __shfl_xor_sync(0xffffffffu, rs, off);
            l_r[r] = l_r[r] * alpha + rs;
#pragma unroll
            for (int c = 0; c < 4; c++) {
                acc[r][c] *= alpha;
                Ps[4*ty + r][4*tx + c] = s[r][c];
            }
        }
        __syncthreads();  // Ps complete before PV reads other threads' columns

        // PV: acc[r][c] += P[4ty+r][j] * V[j][4tx+c]
#pragma unroll 8
        for (int j = 0; j < 64; j++) {
            const float4 vv = *(const float4*)&Vs[j][4*tx];
            const float vc[4] = {vv.x, vv.y, vv.z, vv.w};
            float pr[4];
#pragma unroll
            for (int r = 0; r < 4; r++) pr[r] = Ps[4*ty + r][j];
#pragma unroll
            for (int r = 0; r < 4; r++)
#pragma unroll
                for (int c = 0; c < 4; c++)
                    acc[r][c] += pr[r] * vc[c];
        }
    }

    // epilogue: normalize and write [B,T,C]
#pragma unroll
    for (int r = 0; r < 4; r++) {
        const int qi = q0 + 4*ty + r;
        const float inv_l = 1.f / l_r[r];
        float4 o;
        o.x = acc[r][0] * inv_l;
        o.y = acc[r][1] * inv_l;
        o.z = acc[r][2] * inv_l;
        o.w = acc[r][3] * inv_l;
        *(float4*)&out[((size_t)(b*T_ + qi)) * C_ + h*D_ + 4*tx] = o;
    }
}

// ---------------------------------------------------------------------------
extern "C" void kernel_launch(void* const* d_in, const int* in_sizes, int n_in,
                              void* d_out, int out_size)
{
    const float* x  = (const float*)d_in[0];
    const float* Wq = (const float*)d_in[1];
    const float* bq = (const float*)d_in[2];
    const float* Wk = (const float*)d_in[3];
    const float* bk = (const float*)d_in[4];
    const float* Wv = (const float*)d_in[5];
    const float* bv = (const float*)d_in[6];
    const float* Wo = (const float*)d_in[7];
    const float* bo = (const float*)d_in[8];
    float* out = (float*)d_out;

    float *qp, *kp, *vp, *attp;
    cudaGetSymbolAddress((void**)&qp,   g_q);
    cudaGetSymbolAddress((void**)&kp,   g_k);
    cudaGetSymbolAddress((void**)&vp,   g_v);
    cudaGetSymbolAddress((void**)&attp, g_att);

    const dim3 ggrid(C_/64, M_/64);  // (16, 64)
    gemm64<<<ggrid, 256>>>(x, Wq, bq, qp, 0);
    gemm64<<<ggrid, 256>>>(x, Wk, bk, kp, 0);
    gemm64<<<ggrid, 256>>>(x, Wv, bv, vp, 0);

    const int rtotal = B_*H_*T_*(D_/2);
    rope_kernel<<<rtotal/256, 256>>>(qp, kp);

    const size_t smem = (size_t)(64*65 + 64*KT_STRIDE + 64*64 + 64*65) * sizeof(float);
    cudaFuncSetAttribute(attn_kernel, cudaFuncAttributeMaxDynamicSharedMemorySize, (int)smem);
    attn_kernel<<<dim3(T_/64, B_*H_), 256, smem>>>(qp, kp, vp, attp);

    gemm64<<<ggrid, 256>>>(attp, Wo, bo, out, 1);
}

// round 3
// speedup vs baseline: 1.5812x; 1.5812x over previous
#include <cuda_runtime.h>
#include <math.h>

#define B_ 2
#define T_ 2048
#define C_ 1024
#define H_ 16
#define D_ 64
#define M_ (B_*T_)
#define SCALE 0.125f   // 1/sqrt(64)

typedef unsigned long long ull;

// Packed fp32x2 helpers (sm_103a FFMA2 path)
#define PACK2(d, lo, hi)  asm("mov.b64 %0, {%1,%2};" : "=l"(d) : "f"(lo), "f"(hi))
#define UNPACK2(lo, hi, s) asm("mov.b64 {%0,%1}, %2;" : "=f"(lo), "=f"(hi) : "l"(s))
#define FMA2(d, a, b)     asm("fma.rn.f32x2 %0, %1, %2, %0;" : "+l"(d) : "l"(a), "l"(b))
#define MUL2(d, a, b)     asm("mul.rn.f32x2 %0, %1, %2;" : "=l"(d) : "l"(a), "l"(b))

// Scratch (allocation-free contract: __device__ globals)
__device__ float  g_q[B_*H_*T_*D_];
__device__ float  g_k[B_*H_*T_*D_];
__device__ float  g_v[B_*H_*T_*D_];
__device__ float  g_att[B_*T_*C_];
__device__ float2 g_cs[T_*32];     // RoPE cos/sin table

// ---------------------------------------------------------------------------
// RoPE table: 65536 threads, fp64 once. cos/sin(t * 10000^(-2i/64))
// ---------------------------------------------------------------------------
__global__ void rope_table(float2* __restrict__ tab)
{
    const int idx = blockIdx.x * blockDim.x + threadIdx.x;
    if (idx >= T_*32) return;
    const int t = idx >> 5, i = idx & 31;
    const double inv = pow(10000.0, -(double)(2*i) / 64.0);
    const double ang = (double)t * inv;
    tab[idx] = make_float2((float)cos(ang), (float)sin(ang));
}

// ---------------------------------------------------------------------------
// GEMM core: out = A[M,1024] @ W[N,1024]^T + bias, 128x128 tile, 8x8/thread,
// transposed smem (k-major), packed f32x2 FMAs.
// mode 0: scatter [B,H,T,D] + RoPE.  mode 1: scatter, no rope.  mode 2: plain.
// ---------------------------------------------------------------------------
__device__ __forceinline__
void gemm_body(const float* __restrict__ A, const float* __restrict__ W,
               const float* __restrict__ bias, float* __restrict__ out,
               const float2* __restrict__ cs, int mode)
{
    __shared__ float As[16][132];
    __shared__ float Ws[16][132];
    const int tid = threadIdx.x;
    const int tx = tid & 15, ty = tid >> 4;
    const int m0 = blockIdx.y << 7, n0 = blockIdx.x << 7;

    ull acc[8][4];
#pragma unroll
    for (int r = 0; r < 8; r++)
#pragma unroll
        for (int p = 0; p < 4; p++) acc[r][p] = 0ull;

    for (int k0 = 0; k0 < C_; k0 += 16) {
        __syncthreads();
#pragma unroll
        for (int ld = 0; ld < 2; ld++) {
            const int job = tid + (ld << 8);
            const int r = job >> 2, v = job & 3;
            const float4 a4 = *(const float4*)&A[(size_t)(m0 + r) * C_ + k0 + 4*v];
            As[4*v+0][r] = a4.x; As[4*v+1][r] = a4.y;
            As[4*v+2][r] = a4.z; As[4*v+3][r] = a4.w;
            const float4 w4 = *(const float4*)&W[(size_t)(n0 + r) * C_ + k0 + 4*v];
            Ws[4*v+0][r] = w4.x; Ws[4*v+1][r] = w4.y;
            Ws[4*v+2][r] = w4.z; Ws[4*v+3][r] = w4.w;
        }
        __syncthreads();
#pragma unroll
        for (int kk = 0; kk < 16; kk++) {
            const float4 aA = *(const float4*)&As[kk][8*ty];
            const float4 aB = *(const float4*)&As[kk][8*ty + 4];
            const ulonglong2 wA = *(const ulonglong2*)&Ws[kk][8*tx];
            const ulonglong2 wB = *(const ulonglong2*)&Ws[kk][8*tx + 4];
            const float a[8] = {aA.x, aA.y, aA.z, aA.w, aB.x, aB.y, aB.z, aB.w};
            ull pa[8];
#pragma unroll
            for (int r = 0; r < 8; r++) PACK2(pa[r], a[r], a[r]);
#pragma unroll
            for (int r = 0; r < 8; r++) {
                FMA2(acc[r][0], pa[r], wA.x);
                FMA2(acc[r][1], pa[r], wA.y);
                FMA2(acc[r][2], pa[r], wB.x);
                FMA2(acc[r][3], pa[r], wB.y);
            }
        }
    }

    const int n_base = n0 + 8*tx;
    const float4 b0 = *(const float4*)&bias[n_base];
    const float4 b1 = *(const float4*)&bias[n_base + 4];
    const float bb[8] = {b0.x, b0.y, b0.z, b0.w, b1.x, b1.y, b1.z, b1.w};

#pragma unroll
    for (int r = 0; r < 8; r++) {
        const int m = m0 + 8*ty + r;
        float o[8];
#pragma unroll
        for (int p = 0; p < 4; p++) UNPACK2(o[2*p], o[2*p+1], acc[r][p]);
#pragma unroll
        for (int j = 0; j < 8; j++) o[j] += bb[j];

        if (mode == 0) {  // RoPE on (even,odd) pairs
            const int t = m & (T_-1);
#pragma unroll
            for (int p = 0; p < 4; p++) {
                const int i = ((n_base + 2*p) & 63) >> 1;
                const float2 csv = cs[t*32 + i];
                const float x1 = o[2*p], x2 = o[2*p+1];
                o[2*p]   = x1*csv.x - x2*csv.y;
                o[2*p+1] = x1*csv.y + x2*csv.x;
            }
        }

        float4 o0 = {o[0], o[1], o[2], o[3]};
        float4 o1 = {o[4], o[5], o[6], o[7]};
        if (mode <= 1) {  // scatter to [B,H,T,D]
            const int b = m >> 11, t = m & (T_-1);
            const int h = n_base >> 6, d = n_base & 63;
            float* dst = out + (((size_t)(b*H_ + h) * T_) + t) * D_ + d;
            *(float4*)dst = o0;
            *(float4*)(dst + 4) = o1;
        } else {
            float* dst = out + (size_t)m * C_ + n_base;
            *(float4*)dst = o0;
            *(float4*)(dst + 4) = o1;
        }
    }
}

__global__ __launch_bounds__(256, 2)
void qkv_gemm(const float* __restrict__ x,
              const float* __restrict__ Wq, const float* __restrict__ bq,
              const float* __restrict__ Wk, const float* __restrict__ bk,
              const float* __restrict__ Wv, const float* __restrict__ bv,
              float* __restrict__ q, float* __restrict__ k, float* __restrict__ v,
              const float2* __restrict__ cs)
{
    const int z = blockIdx.z;
    const float* W = (z == 0) ? Wq : (z == 1) ? Wk : Wv;
    const float* b = (z == 0) ? bq : (z == 1) ? bk : bv;
    float* o       = (z == 0) ? q  : (z == 1) ? k  : v;
    gemm_body(x, W, b, o, cs, (z < 2) ? 0 : 1);
}

__global__ __launch_bounds__(256, 2)
void out_gemm(const float* __restrict__ A, const float* __restrict__ W,
              const float* __restrict__ bias, float* __restrict__ out)
{
    gemm_body(A, W, bias, out, nullptr, 2);
}

// ---------------------------------------------------------------------------
// Flash attention, causal. 64 queries x 64 keys per tile, 256 threads,
// 4x4/thread with packed f32x2. Q, K, P transposed in smem for LDS.128.
// ---------------------------------------------------------------------------
__global__ __launch_bounds__(256)
void attn_kernel(const float* __restrict__ q, const float* __restrict__ k,
                 const float* __restrict__ v, float* __restrict__ out)
{
    extern __shared__ float smem[];
    float (*Qt)[68] = (float(*)[68]) smem;                      // Qt[d][row]
    float (*Kt)[68] = (float(*)[68])(smem + 64*68);             // Kt[d][col]
    float (*Vs)[64] = (float(*)[64])(smem + 2*64*68);           // Vs[j][d]
    float (*Pt)[68] = (float(*)[68])(smem + 2*64*68 + 64*64);   // Pt[j][row]

    const int tid = threadIdx.x;
    const int tx = tid & 15, ty = tid >> 4;
    const int bh = blockIdx.y;
    const int b = bh >> 4, h = bh & (H_-1);
    const int q0 = blockIdx.x << 6;

    const float* qb = q + (size_t)bh * T_ * D_;
    const float* kb = k + (size_t)bh * T_ * D_;
    const float* vb = v + (size_t)bh * T_ * D_;

    // load Q tile transposed
#pragma unroll
    for (int ld = 0; ld < 4; ld++) {
        const int job = tid + (ld << 8);
        const int r = job >> 4, vv = job & 15;
        const float4 q4 = *(const float4*)&qb[(size_t)(q0 + r) * D_ + 4*vv];
        Qt[4*vv+0][r] = q4.x; Qt[4*vv+1][r] = q4.y;
        Qt[4*vv+2][r] = q4.z; Qt[4*vv+3][r] = q4.w;
    }

    float m_r[4], l_r[4];
    ull acc[2][4];  // packed along rows: pairs (r0,r1),(r2,r3) x 4 cols
#pragma unroll
    for (int r = 0; r < 4; r++) { m_r[r] = -1e30f; l_r[r] = 0.f; }
#pragma unroll
    for (int g = 0; g < 2; g++)
#pragma unroll
        for (int c = 0; c < 4; c++) acc[g][c] = 0ull;

    const int ntiles = (q0 >> 6) + 1;
    for (int kt = 0; kt < ntiles; kt++) {
        const int k0 = kt << 6;
        __syncthreads();
#pragma unroll
        for (int ld = 0; ld < 4; ld++) {
            const int job = tid + (ld << 8);
            const int r = job >> 4, vv = job & 15;
            const float4 k4 = *(const float4*)&kb[(size_t)(k0 + r) * D_ + 4*vv];
            Kt[4*vv+0][r] = k4.x; Kt[4*vv+1][r] = k4.y;
            Kt[4*vv+2][r] = k4.z; Kt[4*vv+3][r] = k4.w;
            *(float4*)&Vs[r][4*vv] = *(const float4*)&vb[(size_t)(k0 + r) * D_ + 4*vv];
        }
        __syncthreads();

        // scores (packed along cols)
        ull sp[4][2];
#pragma unroll
        for (int r = 0; r < 4; r++) { sp[r][0] = 0ull; sp[r][1] = 0ull; }
#pragma unroll 4
        for (int d = 0; d < D_; d++) {
            const ulonglong2 kv = *(const ulonglong2*)&Kt[d][4*tx];
            const float4 qv = *(const float4*)&Qt[d][4*ty];
            const float qa[4] = {qv.x, qv.y, qv.z, qv.w};
            ull pq[4];
#pragma unroll
            for (int r = 0; r < 4; r++) PACK2(pq[r], qa[r], qa[r]);
#pragma unroll
            for (int r = 0; r < 4; r++) {
                FMA2(sp[r][0], pq[r], kv.x);
                FMA2(sp[r][1], pq[r], kv.y);
            }
        }

        // unpack, mask, online softmax
        float s[4][4], alpha[4];
#pragma unroll
        for (int r = 0; r < 4; r++) {
            UNPACK2(s[r][0], s[r][1], sp[r][0]);
            UNPACK2(s[r][2], s[r][3], sp[r][1]);
            const int qi = q0 + 4*ty + r;
            float rm = -1e30f;
#pragma unroll
            for (int c = 0; c < 4; c++) {
                const int kj = k0 + 4*tx + c;
                s[r][c] = (kj <= qi) ? s[r][c] * SCALE : -1e30f;
                rm = fmaxf(rm, s[r][c]);
            }
#pragma unroll
            for (int off = 8; off > 0; off >>= 1)
                rm = fmaxf(rm, __shfl_xor_sync(0xffffffffu, rm, off));
            const float mnew = fmaxf(m_r[r], rm);
            alpha[r] = __expf(m_r[r] - mnew);
            m_r[r] = mnew;
            float rs = 0.f;
#pragma unroll
            for (int c = 0; c < 4; c++) {
                const float p = __expf(s[r][c] - mnew);
                s[r][c] = p;
                rs += p;
            }
#pragma unroll
            for (int off = 8; off > 0; off >>= 1)
                rs += __shfl_xor_sync(0xffffffffu, rs, off);
            l_r[r] = l_r[r] * alpha[r] + rs;
        }

        // rescale packed accumulator
        ull pal0, pal1;
        PACK2(pal0, alpha[0], alpha[1]);
        PACK2(pal1, alpha[2], alpha[3]);
#pragma unroll
        for (int c = 0; c < 4; c++) {
            MUL2(acc[0][c], acc[0][c], pal0);
            MUL2(acc[1][c], acc[1][c], pal1);
        }

        // store P transposed: column vectors are contiguous -> STS.128
#pragma unroll
        for (int c = 0; c < 4; c++) {
            float4 col = {s[0][c], s[1][c], s[2][c], s[3][c]};
            *(float4*)&Pt[4*tx + c][4*ty] = col;
        }
        __syncthreads();

        // PV (acc packed along rows)
#pragma unroll 4
        for (int j = 0; j < 64; j++) {
            const ulonglong2 pv = *(const ulonglong2*)&Pt[j][4*ty];
            const float4 vv = *(const float4*)&Vs[j][4*tx];
            const float va[4] = {vv.x, vv.y, vv.z, vv.w};
            ull pw[4];
#pragma unroll
            for (int c = 0; c < 4; c++) PACK2(pw[c], va[c], va[c]);
#pragma unroll
            for (int c = 0; c < 4; c++) {
                FMA2(acc[0][c], pv.x, pw[c]);
                FMA2(acc[1][c], pv.y, pw[c]);
            }
        }
    }

    // epilogue: normalize and write [B,T,C]
    float oacc[4][4];
#pragma unroll
    for (int c = 0; c < 4; c++) {
        UNPACK2(oacc[0][c], oacc[1][c], acc[0][c]);
        UNPACK2(oacc[2][c], oacc[3][c], acc[1][c]);
    }
#pragma unroll
    for (int r = 0; r < 4; r++) {
        const int qi = q0 + 4*ty + r;
        const float inv_l = 1.f / l_r[r];
        float4 o = {oacc[r][0]*inv_l, oacc[r][1]*inv_l, oacc[r][2]*inv_l, oacc[r][3]*inv_l};
        *(float4*)&out[((size_t)(b*T_ + qi)) * C_ + h*D_ + 4*tx] = o;
    }
}

// ---------------------------------------------------------------------------
extern "C" void kernel_launch(void* const* d_in, const int* in_sizes, int n_in,
                              void* d_out, int out_size)
{
    const float* x  = (const float*)d_in[0];
    const float* Wq = (const float*)d_in[1];
    const float* bq = (const float*)d_in[2];
    const float* Wk = (const float*)d_in[3];
    const float* bk = (const float*)d_in[4];
    const float* Wv = (const float*)d_in[5];
    const float* bv = (const float*)d_in[6];
    const float* Wo = (const float*)d_in[7];
    const float* bo = (const float*)d_in[8];
    float* out = (float*)d_out;

    float *qp, *kp, *vp, *attp;
    float2* csp;
    cudaGetSymbolAddress((void**)&qp,   g_q);
    cudaGetSymbolAddress((void**)&kp,   g_k);
    cudaGetSymbolAddress((void**)&vp,   g_v);
    cudaGetSymbolAddress((void**)&attp, g_att);
    cudaGetSymbolAddress((void**)&csp,  g_cs);

    rope_table<<<(T_*32)/256, 256>>>(csp);

    qkv_gemm<<<dim3(C_/128, M_/128, 3), 256>>>(x, Wq, bq, Wk, bk, Wv, bv,
                                               qp, kp, vp, csp);

    const size_t smem = (size_t)(64*68*3 + 64*64) * sizeof(float);
    cudaFuncSetAttribute(attn_kernel, cudaFuncAttributeMaxDynamicSharedMemorySize, (int)smem);
    attn_kernel<<<dim3(T_/64, B_*H_), 256, smem>>>(qp, kp, vp, attp);

    out_gemm<<<dim3(C_/128, M_/128), 256>>>(attp, Wo, bo, out);
}

// round 4
// speedup vs baseline: 1.5967x; 1.0098x over previous
#include <cuda_runtime.h>
#include <math.h>

#define B_ 2
#define T_ 2048
#define C_ 1024
#define H_ 16
#define D_ 64
#define M_ (B_*T_)
#define SCALE 0.125f   // 1/sqrt(64)

typedef unsigned long long ull;

// Packed fp32x2 helpers (sm_103a FFMA2 path)
#define PACK2(d, lo, hi)  asm("mov.b64 %0, {%1,%2};" : "=l"(d) : "f"(lo), "f"(hi))
#define UNPACK2(lo, hi, s) asm("mov.b64 {%0,%1}, %2;" : "=f"(lo), "=f"(hi) : "l"(s))
#define FMA2(d, a, b)     asm("fma.rn.f32x2 %0, %1, %2, %0;" : "+l"(d) : "l"(a), "l"(b))
#define MUL2(d, a, b)     asm("mul.rn.f32x2 %0, %1, %2;" : "=l"(d) : "l"(a), "l"(b))

// Scratch (allocation-free contract: __device__ globals)
__device__ float  g_q[B_*H_*T_*D_];
__device__ float  g_k[B_*H_*T_*D_];
__device__ float  g_v[B_*H_*T_*D_];
__device__ float  g_att[B_*T_*C_];
__device__ float2 g_cs[T_*32];     // RoPE cos/sin table

// ---------------------------------------------------------------------------
// RoPE table: 65536 threads, fp64 once. cos/sin(t * 10000^(-2i/64))
// ---------------------------------------------------------------------------
__global__ void rope_table(float2* __restrict__ tab)
{
    const int idx = blockIdx.x * blockDim.x + threadIdx.x;
    if (idx >= T_*32) return;
    const int t = idx >> 5, i = idx & 31;
    const double inv = pow(10000.0, -(double)(2*i) / 64.0);
    const double ang = (double)t * inv;
    tab[idx] = make_float2((float)cos(ang), (float)sin(ang));
}

// ---------------------------------------------------------------------------
// GEMM core: out = A[M,1024] @ W[N,1024]^T + bias, 128x128 tile, 8x8/thread,
// transposed smem (k-major), packed f32x2 FMAs.
// mode 0: scatter [B,H,T,D] + RoPE.  mode 1: scatter, no rope.  mode 2: plain.
// ---------------------------------------------------------------------------
__device__ __forceinline__
void gemm_body(const float* __restrict__ A, const float* __restrict__ W,
               const float* __restrict__ bias, float* __restrict__ out,
               const float2* __restrict__ cs, int mode)
{
    __shared__ float As[16][132];
    __shared__ float Ws[16][132];
    const int tid = threadIdx.x;
    const int tx = tid & 15, ty = tid >> 4;
    const int m0 = blockIdx.y << 7, n0 = blockIdx.x << 7;

    ull acc[8][4];
#pragma unroll
    for (int r = 0; r < 8; r++)
#pragma unroll
        for (int p = 0; p < 4; p++) acc[r][p] = 0ull;

    for (int k0 = 0; k0 < C_; k0 += 16) {
        __syncthreads();
#pragma unroll
        for (int ld = 0; ld < 2; ld++) {
            const int job = tid + (ld << 8);
            const int r = job >> 2, v = job & 3;
            const float4 a4 = *(const float4*)&A[(size_t)(m0 + r) * C_ + k0 + 4*v];
            As[4*v+0][r] = a4.x; As[4*v+1][r] = a4.y;
            As[4*v+2][r] = a4.z; As[4*v+3][r] = a4.w;
            const float4 w4 = *(const float4*)&W[(size_t)(n0 + r) * C_ + k0 + 4*v];
            Ws[4*v+0][r] = w4.x; Ws[4*v+1][r] = w4.y;
            Ws[4*v+2][r] = w4.z; Ws[4*v+3][r] = w4.w;
        }
        __syncthreads();
#pragma unroll
        for (int kk = 0; kk < 16; kk++) {
            const float4 aA = *(const float4*)&As[kk][8*ty];
            const float4 aB = *(const float4*)&As[kk][8*ty + 4];
            const ulonglong2 wA = *(const ulonglong2*)&Ws[kk][8*tx];
            const ulonglong2 wB = *(const ulonglong2*)&Ws[kk][8*tx + 4];
            const float a[8] = {aA.x, aA.y, aA.z, aA.w, aB.x, aB.y, aB.z, aB.w};
            ull pa[8];
#pragma unroll
            for (int r = 0; r < 8; r++) PACK2(pa[r], a[r], a[r]);
#pragma unroll
            for (int r = 0; r < 8; r++) {
                FMA2(acc[r][0], pa[r], wA.x);
                FMA2(acc[r][1], pa[r], wA.y);
                FMA2(acc[r][2], pa[r], wB.x);
                FMA2(acc[r][3], pa[r], wB.y);
            }
        }
    }

    const int n_base = n0 + 8*tx;
    const float4 b0 = *(const float4*)&bias[n_base];
    const float4 b1 = *(const float4*)&bias[n_base + 4];
    const float bb[8] = {b0.x, b0.y, b0.z, b0.w, b1.x, b1.y, b1.z, b1.w};

#pragma unroll
    for (int r = 0; r < 8; r++) {
        const int m = m0 + 8*ty + r;
        float o[8];
#pragma unroll
        for (int p = 0; p < 4; p++) UNPACK2(o[2*p], o[2*p+1], acc[r][p]);
#pragma unroll
        for (int j = 0; j < 8; j++) o[j] += bb[j];

        if (mode == 0) {  // RoPE on (even,odd) pairs
            const int t = m & (T_-1);
#pragma unroll
            for (int p = 0; p < 4; p++) {
                const int i = ((n_base + 2*p) & 63) >> 1;
                const float2 csv = cs[t*32 + i];
                const float x1 = o[2*p], x2 = o[2*p+1];
                o[2*p]   = x1*csv.x - x2*csv.y;
                o[2*p+1] = x1*csv.y + x2*csv.x;
            }
        }

        float4 o0 = {o[0], o[1], o[2], o[3]};
        float4 o1 = {o[4], o[5], o[6], o[7]};
        if (mode <= 1) {  // scatter to [B,H,T,D]
            const int b = m >> 11, t = m & (T_-1);
            const int h = n_base >> 6, d = n_base & 63;
            float* dst = out + (((size_t)(b*H_ + h) * T_) + t) * D_ + d;
            *(float4*)dst = o0;
            *(float4*)(dst + 4) = o1;
        } else {
            float* dst = out + (size_t)m * C_ + n_base;
            *(float4*)dst = o0;
            *(float4*)(dst + 4) = o1;
        }
    }
}

__global__ __launch_bounds__(256, 2)
void qkv_gemm(const float* __restrict__ x,
              const float* __restrict__ Wq, const float* __restrict__ bq,
              const float* __restrict__ Wk, const float* __restrict__ bk,
              const float* __restrict__ Wv, const float* __restrict__ bv,
              float* __restrict__ q, float* __restrict__ k, float* __restrict__ v,
              const float2* __restrict__ cs)
{
    const int z = blockIdx.z;
    const float* W = (z == 0) ? Wq : (z == 1) ? Wk : Wv;
    const float* b = (z == 0) ? bq : (z == 1) ? bk : bv;
    float* o       = (z == 0) ? q  : (z == 1) ? k  : v;
    gemm_body(x, W, b, o, cs, (z < 2) ? 0 : 1);
}

__global__ __launch_bounds__(256, 2)
void out_gemm(const float* __restrict__ A, const float* __restrict__ W,
              const float* __restrict__ bias, float* __restrict__ out)
{
    gemm_body(A, W, bias, out, nullptr, 2);
}

// ---------------------------------------------------------------------------
// Flash attention, causal. 64 queries x 64 keys per tile, 256 threads,
// 4x4/thread with packed f32x2. Q, K, P transposed in smem for LDS.128.
// ---------------------------------------------------------------------------
__global__ __launch_bounds__(256)
void attn_kernel(const float* __restrict__ q, const float* __restrict__ k,
                 const float* __restrict__ v, float* __restrict__ out)
{
    extern __shared__ float smem[];
    float (*Qt)[68] = (float(*)[68]) smem;                      // Qt[d][row]
    float (*Kt)[68] = (float(*)[68])(smem + 64*68);             // Kt[d][col]
    float (*Vs)[64] = (float(*)[64])(smem + 2*64*68);           // Vs[j][d]
    float (*Pt)[68] = (float(*)[68])(smem + 2*64*68 + 64*64);   // Pt[j][row]

    const int tid = threadIdx.x;
    const int tx = tid & 15, ty = tid >> 4;
    const int bh = blockIdx.y;
    const int b = bh >> 4, h = bh & (H_-1);
    const int q0 = blockIdx.x << 6;

    const float* qb = q + (size_t)bh * T_ * D_;
    const float* kb = k + (size_t)bh * T_ * D_;
    const float* vb = v + (size_t)bh * T_ * D_;

    // load Q tile transposed
#pragma unroll
    for (int ld = 0; ld < 4; ld++) {
        const int job = tid + (ld << 8);
        const int r = job >> 4, vv = job & 15;
        const float4 q4 = *(const float4*)&qb[(size_t)(q0 + r) * D_ + 4*vv];
        Qt[4*vv+0][r] = q4.x; Qt[4*vv+1][r] = q4.y;
        Qt[4*vv+2][r] = q4.z; Qt[4*vv+3][r] = q4.w;
    }

    float m_r[4], l_r[4];
    ull acc[2][4];  // packed along rows: pairs (r0,r1),(r2,r3) x 4 cols
#pragma unroll
    for (int r = 0; r < 4; r++) { m_r[r] = -1e30f; l_r[r] = 0.f; }
#pragma unroll
    for (int g = 0; g < 2; g++)
#pragma unroll
        for (int c = 0; c < 4; c++) acc[g][c] = 0ull;

    const int ntiles = (q0 >> 6) + 1;
    for (int kt = 0; kt < ntiles; kt++) {
        const int k0 = kt << 6;
        __syncthreads();
#pragma unroll
        for (int ld = 0; ld < 4; ld++) {
            const int job = tid + (ld << 8);
            const int r = job >> 4, vv = job & 15;
            const float4 k4 = *(const float4*)&kb[(size_t)(k0 + r) * D_ + 4*vv];
            Kt[4*vv+0][r] = k4.x; Kt[4*vv+1][r] = k4.y;
            Kt[4*vv+2][r] = k4.z; Kt[4*vv+3][r] = k4.w;
            *(float4*)&Vs[r][4*vv] = *(const float4*)&vb[(size_t)(k0 + r) * D_ + 4*vv];
        }
        __syncthreads();

        // scores (packed along cols)
        ull sp[4][2];
#pragma unroll
        for (int r = 0; r < 4; r++) { sp[r][0] = 0ull; sp[r][1] = 0ull; }
#pragma unroll 4
        for (int d = 0; d < D_; d++) {
            const ulonglong2 kv = *(const ulonglong2*)&Kt[d][4*tx];
            const float4 qv = *(const float4*)&Qt[d][4*ty];
            const float qa[4] = {qv.x, qv.y, qv.z, qv.w};
            ull pq[4];
#pragma unroll
            for (int r = 0; r < 4; r++) PACK2(pq[r], qa[r], qa[r]);
#pragma unroll
            for (int r = 0; r < 4; r++) {
                FMA2(sp[r][0], pq[r], kv.x);
                FMA2(sp[r][1], pq[r], kv.y);
            }
        }

        // unpack, mask, online softmax
        float s[4][4], alpha[4];
#pragma unroll
        for (int r = 0; r < 4; r++) {
            UNPACK2(s[r][0], s[r][1], sp[r][0]);
            UNPACK2(s[r][2], s[r][3], sp[r][1]);
            const int qi = q0 + 4*ty + r;
            float rm = -1e30f;
#pragma unroll
            for (int c = 0; c < 4; c++) {
                const int kj = k0 + 4*tx + c;
                s[r][c] = (kj <= qi) ? s[r][c] * SCALE : -1e30f;
                rm = fmaxf(rm, s[r][c]);
            }
#pragma unroll
            for (int off = 8; off > 0; off >>= 1)
                rm = fmaxf(rm, __shfl_xor_sync(0xffffffffu, rm, off));
            const float mnew = fmaxf(m_r[r], rm);
            alpha[r] = __expf(m_r[r] - mnew);
            m_r[r] = mnew;
            float rs = 0.f;
#pragma unroll
            for (int c = 0; c < 4; c++) {
                const float p = __expf(s[r][c] - mnew);
                s[r][c] = p;
                rs += p;
            }
#pragma unroll
            for (int off = 8; off > 0; off >>= 1)
                rs += __shfl_xor_sync(0xffffffffu, rs, off);
            l_r[r] = l_r[r] * alpha[r] + rs;
        }

        // rescale packed accumulator
        ull pal0, pal1;
        PACK2(pal0, alpha[0], alpha[1]);
        PACK2(pal1, alpha[2], alpha[3]);
#pragma unroll
        for (int c = 0; c < 4; c++) {
            MUL2(acc[0][c], acc[0][c], pal0);
            MUL2(acc[1][c], acc[1][c], pal1);
        }

        // store P transposed: column vectors are contiguous -> STS.128
#pragma unroll
        for (int c = 0; c < 4; c++) {
            float4 col = {s[0][c], s[1][c], s[2][c], s[3][c]};
            *(float4*)&Pt[4*tx + c][4*ty] = col;
        }
        __syncthreads();

        // PV (acc packed along rows)
#pragma unroll 4
        for (int j = 0; j < 64; j++) {
            const ulonglong2 pv = *(const ulonglong2*)&Pt[j][4*ty];
            const float4 vv = *(const float4*)&Vs[j][4*tx];
            const float va[4] = {vv.x, vv.y, vv.z, vv.w};
            ull pw[4];
#pragma unroll
            for (int c = 0; c < 4; c++) PACK2(pw[c], va[c], va[c]);
#pragma unroll
            for (int c = 0; c < 4; c++) {
                FMA2(acc[0][c], pv.x, pw[c]);
                FMA2(acc[1][c], pv.y, pw[c]);
            }
        }
    }

    // epilogue: normalize and write [B,T,C]
    float oacc[4][4];
#pragma unroll
    for (int c = 0; c < 4; c++) {
        UNPACK2(oacc[0][c], oacc[1][c], acc[0][c]);
        UNPACK2(oacc[2][c], oacc[3][c], acc[1][c]);
    }
#pragma unroll
    for (int r = 0; r < 4; r++) {
        const int qi = q0 + 4*ty + r;
        const float inv_l = 1.f / l_r[r];
        float4 o = {oacc[r][0]*inv_l, oacc[r][1]*inv_l, oacc[r][2]*inv_l, oacc[r][3]*inv_l};
        *(float4*)&out[((size_t)(b*T_ + qi)) * C_ + h*D_ + 4*tx] = o;
    }
}

// ---------------------------------------------------------------------------
extern "C" void kernel_launch(void* const* d_in, const int* in_sizes, int n_in,
                              void* d_out, int out_size)
{
    const float* x  = (const float*)d_in[0];
    const float* Wq = (const float*)d_in[1];
    const float* bq = (const float*)d_in[2];
    const float* Wk = (const float*)d_in[3];
    const float* bk = (const float*)d_in[4];
    const float* Wv = (const float*)d_in[5];
    const float* bv = (const float*)d_in[6];
    const float* Wo = (const float*)d_in[7];
    const float* bo = (const float*)d_in[8];
    float* out = (float*)d_out;

    float *qp, *kp, *vp, *attp;
    float2* csp;
    cudaGetSymbolAddress((void**)&qp,   g_q);
    cudaGetSymbolAddress((void**)&kp,   g_k);
    cudaGetSymbolAddress((void**)&vp,   g_v);
    cudaGetSymbolAddress((void**)&attp, g_att);
    cudaGetSymbolAddress((void**)&csp,  g_cs);

    rope_table<<<(T_*32)/256, 256>>>(csp);

    qkv_gemm<<<dim3(C_/128, M_/128, 3), 256>>>(x, Wq, bq, Wk, bk, Wv, bv,
                                               qp, kp, vp, csp);

    const size_t smem = (size_t)(64*68*3 + 64*64) * sizeof(float);
    cudaFuncSetAttribute(attn_kernel, cudaFuncAttributeMaxDynamicSharedMemorySize, (int)smem);
    attn_kernel<<<dim3(T_/64, B_*H_), 256, smem>>>(qp, kp, vp, attp);

    out_gemm<<<dim3(C_/128, M_/128), 256>>>(attp, Wo, bo, out);
}